// round 5
// baseline (speedup 1.0000x reference)
#include <cuda_runtime.h>
#include <cuda_bf16.h>
#include <cstdint>
#include <cstddef>

typedef unsigned long long ull;

#define B_  64
#define S_  200
#define T_  199
#define H_  256
#define G4  1024
#define NI_ 50000

#define CL  8           // CTAs per cluster
#define NCL 16          // clusters (16*4 = 64 batches)
#define THR 512
#define K1_BLOCKS 1592  // 1592*8 warps = 199*64 (b,t) pairs exactly

// ------------------------- device scratch (no allocs allowed) ---------------
__device__ __align__(16) float g_xp[(size_t)T_ * B_ * G4];      // xp + bias, [t][b][1024]
__device__ __align__(16) float g_states[(size_t)T_ * B_ * H_];  // masked h outputs [t][b][256]
__device__ unsigned char g_mask[T_ * B_];
__device__ unsigned g_k3done;
__device__ float2 g_part[K1_BLOCKS];

// ------------------------- helpers ------------------------------------------
__device__ __forceinline__ ull pk2(float lo, float hi) {
    ull r; asm("mov.b64 %0, {%1, %2};" : "=l"(r) : "f"(lo), "f"(hi)); return r;
}
__device__ __forceinline__ void upk2(ull v, float& lo, float& hi) {
    asm("mov.b64 {%0, %1}, %2;" : "=f"(lo), "=f"(hi) : "l"(v));
}
__device__ __forceinline__ void fma2(ull& acc, ull a, ull b) {
    asm("fma.rn.f32x2 %0, %1, %2, %0;" : "+l"(acc) : "l"(a), "l"(b));
}
__device__ __forceinline__ ull add2(ull a, ull b) {
    ull r; asm("add.rn.f32x2 %0, %1, %2;" : "=l"(r) : "l"(a), "l"(b)); return r;
}
__device__ __forceinline__ float sig_(float x) {
    return __fdividef(1.f, 1.f + __expf(-x));
}
__device__ __forceinline__ float tanh_(float x) {
    float a = fabsf(x);
    float e = __expf(-2.f * a);
    float r = __fdividef(1.f - e, 1.f + e);
    return copysignf(r, x);
}
__device__ __forceinline__ unsigned smem_u32(const void* p) {
    unsigned a;
    asm("{ .reg .u64 t; cvta.to.shared.u64 t, %1; cvt.u32.u64 %0, t; }" : "=r"(a) : "l"(p));
    return a;
}
__device__ __forceinline__ unsigned ctarank_() {
    unsigned r; asm("mov.u32 %0, %%cluster_ctarank;" : "=r"(r)); return r;
}
__device__ __forceinline__ unsigned mapa_(unsigned addr, unsigned rank) {
    unsigned r; asm("mapa.shared::cluster.u32 %0, %1, %2;" : "=r"(r) : "r"(addr), "r"(rank));
    return r;
}
__device__ __forceinline__ void st_cl64(unsigned addr, ull v) {
    asm volatile("st.shared::cluster.b64 [%0], %1;" :: "r"(addr), "l"(v) : "memory");
}
__device__ __forceinline__ void mbar_init(unsigned addr, unsigned cnt) {
    asm volatile("mbarrier.init.shared.b64 [%0], %1;" :: "r"(addr), "r"(cnt) : "memory");
}
__device__ __forceinline__ void mbar_arrive_cl(unsigned addr) {
    asm volatile("mbarrier.arrive.shared::cluster.b64 _, [%0];" :: "r"(addr) : "memory");
}
__device__ __forceinline__ void fence_cl() {
    asm volatile("fence.acq_rel.cluster;" ::: "memory");
}
__device__ __forceinline__ void mbar_wait_cl(unsigned addr, int parity) {
    asm volatile(
        "{\n\t.reg .pred P;\n\t"
        "WL_%=:\n\t"
        "mbarrier.try_wait.parity.acquire.cluster.shared::cta.b64 P, [%0], %1, 0x989680;\n\t"
        "@P bra.uni WD_%=;\n\t"
        "bra.uni WL_%=;\n\t"
        "WD_%=:\n\t}"
        :: "r"(addr), "r"(parity) : "memory");
}
__device__ __forceinline__ void cluster_sync_() {
    asm volatile("barrier.cluster.arrive.aligned;" ::: "memory");
    asm volatile("barrier.cluster.wait.aligned;" ::: "memory");
}

// ============================================================================
// K1: x_proj (+bias) -> g_xp, mask bytes, reset k3 flag. One warp per (b,t).
// ============================================================================
__global__ void k1_prep(const int* __restrict__ items, const int* __restrict__ actions,
                        const float* __restrict__ WihT, const float* __restrict__ b_lstm) {
    if (blockIdx.x == 0 && threadIdx.x == 0) g_k3done = 0u;
    int gw = blockIdx.x * 8 + (threadIdx.x >> 5);
    int lane = threadIdx.x & 31;
    if (gw >= T_ * B_) return;
    int b = gw & 63, t = gw >> 6;
    int it = items[b * S_ + t];
    int ac = actions[b * S_ + t];
    bool m = (it != 0);
    const float4* ra = (const float4*)(WihT + (size_t)it * G4);
    const float4* rb = (const float4*)(WihT + (size_t)(NI_ + ac) * G4);
    const float4* bi = (const float4*)b_lstm;
    float4* dst = (float4*)(g_xp + ((size_t)t * B_ + b) * G4);
#pragma unroll
    for (int p = 0; p < 8; p++) {
        int idx = lane + 32 * p;
        float4 bv = bi[idx];
        float4 o;
        if (m) {
            float4 a = ra[idx], c = rb[idx];
            o = make_float4(a.x + c.x + bv.x, a.y + c.y + bv.y,
                            a.z + c.z + bv.z, a.w + c.w + bv.w);
        } else {
            o = bv;
        }
        dst[idx] = o;
    }
    if (lane == 0) g_mask[t * B_ + b] = m ? 1 : 0;
}

// ============================================================================
// K2: LSTM recurrence. 16 independent clusters of 8 CTAs; each cluster owns
// 4 batch elements. h exchanged via DSMEM broadcast + cluster mbarriers.
// CTA rank r owns h-elems [32r,32r+32) x 4 gates = 128 gate rows, K=256,
// weights register-resident (64 floats/thread @ 512 threads).
// ============================================================================
__global__ void __launch_bounds__(THR, 1) __cluster_dims__(CL, 1, 1)
k2_lstm(const float* __restrict__ Whh) {
    __shared__ __align__(16) float smh[2][256][4];   // h double buffer [buf][j][batch]
    __shared__ __align__(16) ull  smp[16][128][2];   // partials [warp][col][pair]
    __shared__ __align__(16) ull  smg[256];          // gates [col][pair]
    __shared__ __align__(8)  ull  mbar[2];

    const int tid = threadIdx.x;
    const unsigned rank = ctarank_();
    const int q = blockIdx.x >> 3;        // cluster id -> batches 4q..4q+3
    const int w = tid >> 5;               // K-slice warp: j in [16w,16w+16)
    const int l = tid & 31;               // lane = h-elem e within CTA

    // zero both h buffers; init barriers (count = 8 producers per phase)
    for (int i = tid; i < 2 * 256; i += THR)
        *(float4*)&smh[0][0][0 + i * 4] = make_float4(0.f, 0.f, 0.f, 0.f);
    if (tid < 2) mbar_init(smem_u32(&mbar[tid]), CL);
    __syncthreads();
    cluster_sync_();   // peers' zero + barrier init visible before any remote op

    // weights: W[g][jj] = Whh[g*256 + 32*rank + l][16w + jj]
    float W[4][16];
    {
        const int R0 = 32 * (int)rank + l;
#pragma unroll
        for (int g = 0; g < 4; g++) {
            const float4* wr = (const float4*)(Whh + (size_t)(g * 256 + R0) * H_ + w * 16);
#pragma unroll
            for (int q4 = 0; q4 < 4; q4++) {
                float4 v = wr[q4];
                W[g][q4 * 4 + 0] = v.x; W[g][q4 * 4 + 1] = v.y;
                W[g][q4 * 4 + 2] = v.z; W[g][q4 * 4 + 3] = v.w;
            }
        }
    }

    const int b0 = q * 4;

    // assembly role (tid < 256): (col ca, pair pa)
    const int ca = tid >> 1, pa = tid & 1;
    const int Ra = (ca >> 5) * 256 + 32 * (int)rank + (ca & 31);  // global gate row
    const float* xpp = g_xp + (size_t)(b0 + 2 * pa) * G4 + Ra;
    float xa = 0.f, xb = 0.f;
    if (tid < 256) { xa = xpp[0]; xb = xpp[G4]; }

    // owner role (tid < 64): (h-elem oe, pair opa), state register-resident
    const int oe = tid >> 1, opa = tid & 1;
    uchar2 mv = make_uchar2(0, 0);
    if (tid < 64) mv = *(const uchar2*)(g_mask + b0 + 2 * opa);
    float c0 = 0.f, c1 = 0.f, h0 = 0.f, h1 = 0.f;

    const unsigned mb0 = smem_u32(&mbar[0]);
    const unsigned mb1 = smem_u32(&mbar[1]);
    int ph0 = 0, ph1 = 0;

    for (int t = 0; t < T_; t++) {
        const int buf = t & 1;
        if (t > 0) {
            if (buf) { mbar_wait_cl(mb1, ph1); ph1 ^= 1; }
            else     { mbar_wait_cl(mb0, ph0); ph0 ^= 1; }
        }

        // ---- compute: acc[g][p] += W[g][jj] * h[16w+jj][2p..2p+1] ----
        ull a00 = 0, a01 = 0, a10 = 0, a11 = 0, a20 = 0, a21 = 0, a30 = 0, a31 = 0;
        {
            const ulonglong2* hb = (const ulonglong2*)&smh[buf][w * 16][0];
#pragma unroll
            for (int jj = 0; jj < 16; jj++) {
                ulonglong2 hx = hb[jj];
                ull w0 = pk2(W[0][jj], W[0][jj]);
                ull w1 = pk2(W[1][jj], W[1][jj]);
                ull w2 = pk2(W[2][jj], W[2][jj]);
                ull w3 = pk2(W[3][jj], W[3][jj]);
                fma2(a00, w0, hx.x); fma2(a01, w0, hx.y);
                fma2(a10, w1, hx.x); fma2(a11, w1, hx.y);
                fma2(a20, w2, hx.x); fma2(a21, w2, hx.y);
                fma2(a30, w3, hx.x); fma2(a31, w3, hx.y);
            }
        }
        *(ulonglong2*)&smp[w][0 * 32 + l][0] = make_ulonglong2(a00, a01);
        *(ulonglong2*)&smp[w][1 * 32 + l][0] = make_ulonglong2(a10, a11);
        *(ulonglong2*)&smp[w][2 * 32 + l][0] = make_ulonglong2(a20, a21);
        *(ulonglong2*)&smp[w][3 * 32 + l][0] = make_ulonglong2(a30, a31);
        __syncthreads();

        // ---- assembly: sum 16 warp partials + xp ----
        if (tid < 256) {
            ull s = smp[0][ca][pa];
#pragma unroll
            for (int ww = 1; ww < 16; ww++) s = add2(s, smp[ww][ca][pa]);
            s = add2(s, pk2(xa, xb));
            smg[ca * 2 + pa] = s;
            if (t + 1 < T_) {  // prefetch xp(t+1): full step of latency cover
                xa = xpp[(size_t)(t + 1) * B_ * G4];
                xb = xpp[(size_t)(t + 1) * B_ * G4 + G4];
            }
        }
        __syncthreads();

        // ---- owners: activations, state update, states store, h broadcast ----
        if (tid < 64) {
            float i0, i1, f0, f1, gg0, gg1, o0, o1;
            upk2(smg[(0 * 32 + oe) * 2 + opa], i0, i1);
            upk2(smg[(1 * 32 + oe) * 2 + opa], f0, f1);
            upk2(smg[(2 * 32 + oe) * 2 + opa], gg0, gg1);
            upk2(smg[(3 * 32 + oe) * 2 + opa], o0, o1);

            float out0, out1;
            {
                float ii = sig_(i0), ff = sig_(f0), gt = tanh_(gg0), oo = sig_(o0);
                float cn = ff * c0 + ii * gt;
                float hn = oo * tanh_(cn);
                if (mv.x) { c0 = cn; h0 = hn; out0 = hn; } else out0 = 0.f;
            }
            {
                float ii = sig_(i1), ff = sig_(f1), gt = tanh_(gg1), oo = sig_(o1);
                float cn = ff * c1 + ii * gt;
                float hn = oo * tanh_(cn);
                if (mv.y) { c1 = cn; h1 = hn; out1 = hn; } else out1 = 0.f;
            }
            const int jg = 32 * (int)rank + oe;
            float* sp = g_states + ((size_t)t * B_ + b0 + 2 * opa) * H_ + jg;
            sp[0]  = out0;
            sp[H_] = out1;

            if (t + 1 < T_) {
                ull hull = pk2(h0, h1);
                unsigned loc = smem_u32(&smh[1 - buf][jg][2 * opa]);
#pragma unroll
                for (int rr = 0; rr < CL; rr++) st_cl64(mapa_(loc, rr), hull);
                mv = *(const uchar2*)(g_mask + (t + 1) * B_ + b0 + 2 * opa);
            }
        }
        __syncthreads();

        // ---- signal h(t+1) ready on every peer's barrier ----
        if (t + 1 < T_ && tid < CL) {
            fence_cl();
            mbar_arrive_cl(mapa_(buf ? mb0 : mb1, tid));
        }
    }
    cluster_sync_();  // no CTA exits while peers' remote ops could be in flight
}

// ============================================================================
// K3: query logits + per-(b,t) NLL; block partials + fused deterministic
// last-block final reduction. One warp per (b,t).
// ============================================================================
__global__ void k3_loss(const int* __restrict__ items, const int* __restrict__ actions,
                        const float* __restrict__ temb, const float* __restrict__ Wq,
                        const float* __restrict__ bq, float* __restrict__ out) {
    __shared__ float2 sred[8];
    __shared__ unsigned slast;
    int gw = blockIdx.x * 8 + (threadIdx.x >> 5);
    int lane = threadIdx.x & 31;
    float nll = 0.f, cnt = 0.f;
    int b = gw & 63, t = gw >> 6;
    int qit = items[b * S_ + t + 1];
    if (qit != 0) {
        const float4* sv = (const float4*)(g_states + ((size_t)t * B_ + b) * H_);
        const float4* ev = (const float4*)(temb + (size_t)qit * H_);
        const float4* w0 = (const float4*)Wq;
        const float4* w1 = (const float4*)(Wq + H_);
        float d0 = 0.f, d1 = 0.f;
#pragma unroll
        for (int p = 0; p < 2; p++) {
            int idx = lane * 2 + p;
            float4 s = sv[idx], e = ev[idx], a = w0[idx], c = w1[idx];
            float es;
            es = e.x * s.x; d0 += es * a.x; d1 += es * c.x;
            es = e.y * s.y; d0 += es * a.y; d1 += es * c.y;
            es = e.z * s.z; d0 += es * a.z; d1 += es * c.z;
            es = e.w * s.w; d0 += es * a.w; d1 += es * c.w;
        }
        ull d = pk2(d0, d1);
#pragma unroll
        for (int off = 16; off; off >>= 1)
            d = add2(d, __shfl_xor_sync(0xffffffffu, d, off));
        upk2(d, d0, d1);
        if (lane == 0) {
            float q0 = d0 + bq[0], q1 = d1 + bq[1];
            int tgt = actions[b * S_ + t + 1];
            float mx = fmaxf(q0, q1), mn = fminf(q0, q1);
            float lse = mx + log1pf(__expf(mn - mx));
            nll = lse - (tgt ? q1 : q0);
            cnt = 1.f;
        }
    }
    if (lane == 0) sred[threadIdx.x >> 5] = make_float2(nll, cnt);
    __syncthreads();
    if (threadIdx.x == 0) {
        float s = 0.f, c = 0.f;
#pragma unroll
        for (int i = 0; i < 8; i++) { s += sred[i].x; c += sred[i].y; }
        g_part[blockIdx.x] = make_float2(s, c);
        __threadfence();
        unsigned o = atomicAdd(&g_k3done, 1u);
        slast = (o == K1_BLOCKS - 1) ? 1u : 0u;
    }
    __syncthreads();
    if (slast) {
        __shared__ float ss[256], sc[256];
        __threadfence();
        float s = 0.f, c = 0.f;
        for (int i = threadIdx.x; i < K1_BLOCKS; i += 256) {
            float2 v = g_part[i];
            s += v.x; c += v.y;
        }
        ss[threadIdx.x] = s; sc[threadIdx.x] = c;
        __syncthreads();
        for (int st = 128; st; st >>= 1) {
            if (threadIdx.x < st) {
                ss[threadIdx.x] += ss[threadIdx.x + st];
                sc[threadIdx.x] += sc[threadIdx.x + st];
            }
            __syncthreads();
        }
        if (threadIdx.x == 0) out[0] = ss[0] / sc[0];
    }
}

// ============================================================================
extern "C" void kernel_launch(void* const* d_in, const int* in_sizes, int n_in,
                              void* d_out, int out_size) {
    const int*   items   = (const int*)d_in[0];
    const int*   actions = (const int*)d_in[1];
    const float* WihT    = (const float*)d_in[2];
    const float* Whh     = (const float*)d_in[3];
    const float* b_lstm  = (const float*)d_in[4];
    const float* temb    = (const float*)d_in[5];
    const float* Wq      = (const float*)d_in[6];
    const float* bq      = (const float*)d_in[7];
    (void)in_sizes; (void)n_in; (void)out_size;

    k1_prep<<<K1_BLOCKS, 256>>>(items, actions, WihT, b_lstm);
    k2_lstm<<<NCL * CL, THR>>>(Whh);
    k3_loss<<<K1_BLOCKS, 256>>>(items, actions, temb, Wq, bq, (float*)d_out);
}

// round 7
// speedup vs baseline: 1.1993x; 1.1993x over previous
#include <cuda_runtime.h>
#include <cuda_bf16.h>
#include <cstdint>
#include <cstddef>

typedef unsigned long long ull;

#define B_  64
#define S_  200
#define T_  199
#define H_  256
#define G4  1024
#define NI_ 50000

#define CL  8           // CTAs per cluster
#define NCL 16          // clusters (16*4 = 64 batches)
#define THR 512
#define K1_BLOCKS 1592  // 1592*8 warps = 199*64 (b,t) pairs exactly

// ------------------------- device scratch (no allocs allowed) ---------------
__device__ __align__(16) float g_xp[(size_t)T_ * B_ * G4];      // xp + bias, [t][b][1024]
__device__ __align__(16) float g_states[(size_t)T_ * B_ * H_];  // masked h outputs [t][b][256]
__device__ unsigned char g_mask[T_ * B_];
__device__ unsigned g_k3done;
__device__ float2 g_part[K1_BLOCKS];

// ------------------------- helpers ------------------------------------------
__device__ __forceinline__ ull pk2(float lo, float hi) {
    ull r; asm("mov.b64 %0, {%1, %2};" : "=l"(r) : "f"(lo), "f"(hi)); return r;
}
__device__ __forceinline__ void upk2(ull v, float& lo, float& hi) {
    asm("mov.b64 {%0, %1}, %2;" : "=f"(lo), "=f"(hi) : "l"(v));
}
__device__ __forceinline__ void fma2(ull& acc, ull a, ull b) {
    asm("fma.rn.f32x2 %0, %1, %2, %0;" : "+l"(acc) : "l"(a), "l"(b));
}
__device__ __forceinline__ ull add2(ull a, ull b) {
    ull r; asm("add.rn.f32x2 %0, %1, %2;" : "=l"(r) : "l"(a), "l"(b)); return r;
}
__device__ __forceinline__ float sig_(float x) {
    return __fdividef(1.f, 1.f + __expf(-x));
}
__device__ __forceinline__ float tanh_(float x) {
    float a = fabsf(x);
    float e = __expf(-2.f * a);
    float r = __fdividef(1.f - e, 1.f + e);
    return copysignf(r, x);
}
__device__ __forceinline__ unsigned smem_u32(const void* p) {
    unsigned a;
    asm("{ .reg .u64 t; cvta.to.shared.u64 t, %1; cvt.u32.u64 %0, t; }" : "=r"(a) : "l"(p));
    return a;
}
__device__ __forceinline__ unsigned ctarank_() {
    unsigned r; asm("mov.u32 %0, %%cluster_ctarank;" : "=r"(r)); return r;
}
__device__ __forceinline__ unsigned mapa_(unsigned addr, unsigned rank) {
    unsigned r; asm("mapa.shared::cluster.u32 %0, %1, %2;" : "=r"(r) : "r"(addr), "r"(rank));
    return r;
}
__device__ __forceinline__ void st_cl64(unsigned addr, ull v) {
    asm volatile("st.shared::cluster.b64 [%0], %1;" :: "r"(addr), "l"(v) : "memory");
}
__device__ __forceinline__ void mbar_init(unsigned addr, unsigned cnt) {
    asm volatile("mbarrier.init.shared.b64 [%0], %1;" :: "r"(addr), "r"(cnt) : "memory");
}
__device__ __forceinline__ void mbar_arrive_rel_cl(unsigned addr) {
    asm volatile("mbarrier.arrive.release.cluster.shared::cluster.b64 _, [%0];"
                 :: "r"(addr) : "memory");
}
__device__ __forceinline__ void mbar_wait_cl(unsigned addr, int parity) {
    asm volatile(
        "{\n\t.reg .pred P;\n\t"
        "WL_%=:\n\t"
        "mbarrier.try_wait.parity.acquire.cluster.shared::cta.b64 P, [%0], %1, 0x989680;\n\t"
        "@P bra.uni WD_%=;\n\t"
        "bra.uni WL_%=;\n\t"
        "WD_%=:\n\t}"
        :: "r"(addr), "r"(parity) : "memory");
}
__device__ __forceinline__ void cluster_sync_() {
    asm volatile("barrier.cluster.arrive.aligned;" ::: "memory");
    asm volatile("barrier.cluster.wait.aligned;" ::: "memory");
}

// ============================================================================
// K1: x_proj (+bias) -> g_xp, mask bytes, reset k3 flag. One warp per (b,t).
// ============================================================================
__global__ void k1_prep(const int* __restrict__ items, const int* __restrict__ actions,
                        const float* __restrict__ WihT, const float* __restrict__ b_lstm) {
    if (blockIdx.x == 0 && threadIdx.x == 0) g_k3done = 0u;
    int gw = blockIdx.x * 8 + (threadIdx.x >> 5);
    int lane = threadIdx.x & 31;
    if (gw >= T_ * B_) return;
    int b = gw & 63, t = gw >> 6;
    int it = items[b * S_ + t];
    int ac = actions[b * S_ + t];
    bool m = (it != 0);
    const float4* ra = (const float4*)(WihT + (size_t)it * G4);
    const float4* rb = (const float4*)(WihT + (size_t)(NI_ + ac) * G4);
    const float4* bi = (const float4*)b_lstm;
    float4* dst = (float4*)(g_xp + ((size_t)t * B_ + b) * G4);
#pragma unroll
    for (int p = 0; p < 8; p++) {
        int idx = lane + 32 * p;
        float4 bv = bi[idx];
        float4 o;
        if (m) {
            float4 a = ra[idx], c = rb[idx];
            o = make_float4(a.x + c.x + bv.x, a.y + c.y + bv.y,
                            a.z + c.z + bv.z, a.w + c.w + bv.w);
        } else {
            o = bv;
        }
        dst[idx] = o;
    }
    if (lane == 0) g_mask[t * B_ + b] = m ? 1 : 0;
}

// profiling-alignment no-ops (2 launches so ncu -s 5 -c 1 lands on k2_lstm)
__global__ void knop() {}

// ============================================================================
// K2: LSTM recurrence. 16 independent clusters of 8 CTAs; cluster owns 4
// batches. CTA rank r owns 128 gate rows (32 h-elems x 4 gates), K=256.
// Thread (ks=tid>>6 in [0,8), u=tid&63) owns cols {u, u+64} with K-slice
// [32ks,32ks+32): 64 weight floats register-resident, 4 f32x2 accumulators.
// h exchange: DSMEM broadcast + mbarrier arrive.release.cluster (no fence).
// ============================================================================
__global__ void __launch_bounds__(THR, 1) __cluster_dims__(CL, 1, 1)
k2_lstm(const float* __restrict__ Whh) {
    __shared__ __align__(16) float smh[2][256][4];   // h double buffer [buf][j][batch]
    __shared__ __align__(16) ull  smp[8][128][2];    // partials [ks][col][pair]
    __shared__ __align__(8)  ull  mbar[2];

    const int tid = threadIdx.x;
    const unsigned rank = ctarank_();
    const int b0 = (blockIdx.x >> 3) * 4;

    const int ks = tid >> 6;        // K-slice (32 j's)
    const int u  = tid & 63;        // first col; second col = u+64

    // zero both h buffers; init barriers (8 arrivals each)
    for (int i = tid; i < 512; i += THR)
        ((float4*)smh)[i] = make_float4(0.f, 0.f, 0.f, 0.f);
    if (tid < 2) mbar_init(smem_u32(&mbar[tid]), CL);
    __syncthreads();
    cluster_sync_();

    // weights for cols u and u+64 over K-slice: col c -> global row (c>>5)*256+32*rank+(c&31)
    float W1[32], W2[32];
    {
        const int r1 = ((u >> 5) & 3) * 256 + 32 * (int)rank + (u & 31);
        const int r2 = (((u + 64) >> 5) & 3) * 256 + 32 * (int)rank + (u & 31);
        const float4* p1 = (const float4*)(Whh + (size_t)r1 * H_ + ks * 32);
        const float4* p2 = (const float4*)(Whh + (size_t)r2 * H_ + ks * 32);
#pragma unroll
        for (int q4 = 0; q4 < 8; q4++) {
            float4 v = p1[q4];
            W1[q4 * 4 + 0] = v.x; W1[q4 * 4 + 1] = v.y; W1[q4 * 4 + 2] = v.z; W1[q4 * 4 + 3] = v.w;
            float4 w = p2[q4];
            W2[q4 * 4 + 0] = w.x; W2[q4 * 4 + 1] = w.y; W2[q4 * 4 + 2] = w.z; W2[q4 * 4 + 3] = w.w;
        }
    }

    // owner role (tid < 64): (oe = tid>>1 in [0,32), opa = tid&1); batches b0+2opa, +1
    const int oe = tid >> 1, opa = tid & 1;
    const int jg = 32 * (int)rank + oe;          // global h index owned
    float c0 = 0.f, c1 = 0.f, h0 = 0.f, h1 = 0.f;
    uchar2 mv = make_uchar2(0, 0);
    float xq0a = 0.f, xq0b = 0.f, xq1a = 0.f, xq1b = 0.f,
          xq2a = 0.f, xq2b = 0.f, xq3a = 0.f, xq3b = 0.f;
    const float* xbase = g_xp + (size_t)(b0 + 2 * opa) * G4 + jg;  // + g*256, +G4 for batch+1
    if (tid < 64) {
        xq0a = xbase[0];       xq0b = xbase[G4];
        xq1a = xbase[256];     xq1b = xbase[G4 + 256];
        xq2a = xbase[512];     xq2b = xbase[G4 + 512];
        xq3a = xbase[768];     xq3b = xbase[G4 + 768];
        mv = *(const uchar2*)(g_mask + b0 + 2 * opa);
    }

    const unsigned mb0 = smem_u32(&mbar[0]);
    const unsigned mb1 = smem_u32(&mbar[1]);
    int ph0 = 0, ph1 = 0;

    for (int t = 0; t < T_; t++) {
        const int buf = t & 1;
        if (t > 0) {
            if (buf) { mbar_wait_cl(mb1, ph1); ph1 ^= 1; }
            else     { mbar_wait_cl(mb0, ph0); ph0 ^= 1; }
        }

        // ---- compute: 4 accumulators (2 cols x 2 batch-pairs) ----
        ull a10 = 0, a11 = 0, a20 = 0, a21 = 0;
        {
            const ulonglong2* hb = (const ulonglong2*)&smh[buf][ks * 32][0];
#pragma unroll
            for (int jj = 0; jj < 32; jj++) {
                ulonglong2 hx = hb[jj];          // batches {0,1},{2,3} of this cluster
                ull w1 = pk2(W1[jj], W1[jj]);
                ull w2 = pk2(W2[jj], W2[jj]);
                fma2(a10, w1, hx.x); fma2(a11, w1, hx.y);
                fma2(a20, w2, hx.x); fma2(a21, w2, hx.y);
            }
        }
        *(ulonglong2*)&smp[ks][u][0]      = make_ulonglong2(a10, a11);
        *(ulonglong2*)&smp[ks][u + 64][0] = make_ulonglong2(a20, a21);
        __syncthreads();

        // ---- owners: reduce 8 K-slices x 4 gates, activations, broadcast ----
        if (tid < 64) {
            ull s0 = smp[0][oe][opa],       s1 = smp[0][32 + oe][opa],
                s2 = smp[0][64 + oe][opa],  s3 = smp[0][96 + oe][opa];
#pragma unroll
            for (int k = 1; k < 8; k++) {
                s0 = add2(s0, smp[k][oe][opa]);
                s1 = add2(s1, smp[k][32 + oe][opa]);
                s2 = add2(s2, smp[k][64 + oe][opa]);
                s3 = add2(s3, smp[k][96 + oe][opa]);
            }
            s0 = add2(s0, pk2(xq0a, xq0b));
            s1 = add2(s1, pk2(xq1a, xq1b));
            s2 = add2(s2, pk2(xq2a, xq2b));
            s3 = add2(s3, pk2(xq3a, xq3b));

            float i0, i1, f0, f1, gg0, gg1, o0, o1;
            upk2(s0, i0, i1); upk2(s1, f0, f1); upk2(s2, gg0, gg1); upk2(s3, o0, o1);

            float out0, out1;
            {
                float ii = sig_(i0), ff = sig_(f0), gt = tanh_(gg0), oo = sig_(o0);
                float cn = ff * c0 + ii * gt;
                float hn = oo * tanh_(cn);
                if (mv.x) { c0 = cn; h0 = hn; out0 = hn; } else out0 = 0.f;
            }
            {
                float ii = sig_(i1), ff = sig_(f1), gt = tanh_(gg1), oo = sig_(o1);
                float cn = ff * c1 + ii * gt;
                float hn = oo * tanh_(cn);
                if (mv.y) { c1 = cn; h1 = hn; out1 = hn; } else out1 = 0.f;
            }

            if (t + 1 < T_) {
                ull hull = pk2(h0, h1);
                unsigned loc = smem_u32(&smh[1 - buf][jg][2 * opa]);
#pragma unroll
                for (int rr = 0; rr < CL; rr++) st_cl64(mapa_(loc, rr), hull);
            }
            asm volatile("bar.sync 1, 64;" ::: "memory");   // owners only (warps 0-1)
            if (t + 1 < T_ && tid < CL)
                mbar_arrive_rel_cl(mapa_(buf ? mb0 : mb1, (unsigned)tid));

            // off critical path: states store + next-step prefetch
            float* sp = g_states + ((size_t)t * B_ + b0 + 2 * opa) * H_ + jg;
            sp[0]  = out0;
            sp[H_] = out1;
            if (t + 1 < T_) {
                const float* xp = xbase + (size_t)(t + 1) * B_ * G4;
                xq0a = xp[0];     xq0b = xp[G4];
                xq1a = xp[256];   xq1b = xp[G4 + 256];
                xq2a = xp[512];   xq2b = xp[G4 + 512];
                xq3a = xp[768];   xq3b = xp[G4 + 768];
                mv = *(const uchar2*)(g_mask + (t + 1) * B_ + b0 + 2 * opa);
            }
        }
        // threads 64..511 fall through to the next mbarrier wait directly
    }
    cluster_sync_();  // no CTA exits while peers' remote ops may be in flight
}

// ============================================================================
// K3: query logits + per-(b,t) NLL; block partials + fused deterministic
// last-block final reduction. One warp per (b,t).
// ============================================================================
__global__ void k3_loss(const int* __restrict__ items, const int* __restrict__ actions,
                        const float* __restrict__ temb, const float* __restrict__ Wq,
                        const float* __restrict__ bq, float* __restrict__ out) {
    __shared__ float2 sred[8];
    __shared__ unsigned slast;
    int gw = blockIdx.x * 8 + (threadIdx.x >> 5);
    int lane = threadIdx.x & 31;
    float nll = 0.f, cnt = 0.f;
    int b = gw & 63, t = gw >> 6;
    int qit = items[b * S_ + t + 1];
    if (qit != 0) {
        const float4* sv = (const float4*)(g_states + ((size_t)t * B_ + b) * H_);
        const float4* ev = (const float4*)(temb + (size_t)qit * H_);
        const float4* w0 = (const float4*)Wq;
        const float4* w1 = (const float4*)(Wq + H_);
        float d0 = 0.f, d1 = 0.f;
#pragma unroll
        for (int p = 0; p < 2; p++) {
            int idx = lane * 2 + p;
            float4 s = sv[idx], e = ev[idx], a = w0[idx], c = w1[idx];
            float es;
            es = e.x * s.x; d0 += es * a.x; d1 += es * c.x;
            es = e.y * s.y; d0 += es * a.y; d1 += es * c.y;
            es = e.z * s.z; d0 += es * a.z; d1 += es * c.z;
            es = e.w * s.w; d0 += es * a.w; d1 += es * c.w;
        }
        ull d = pk2(d0, d1);
#pragma unroll
        for (int off = 16; off; off >>= 1)
            d = add2(d, __shfl_xor_sync(0xffffffffu, d, off));
        upk2(d, d0, d1);
        if (lane == 0) {
            float q0 = d0 + bq[0], q1 = d1 + bq[1];
            int tgt = actions[b * S_ + t + 1];
            float mx = fmaxf(q0, q1), mn = fminf(q0, q1);
            float lse = mx + log1pf(__expf(mn - mx));
            nll = lse - (tgt ? q1 : q0);
            cnt = 1.f;
        }
    }
    if (lane == 0) sred[threadIdx.x >> 5] = make_float2(nll, cnt);
    __syncthreads();
    if (threadIdx.x == 0) {
        float s = 0.f, c = 0.f;
#pragma unroll
        for (int i = 0; i < 8; i++) { s += sred[i].x; c += sred[i].y; }
        g_part[blockIdx.x] = make_float2(s, c);
        __threadfence();
        unsigned o = atomicAdd(&g_k3done, 1u);
        slast = (o == K1_BLOCKS - 1) ? 1u : 0u;
    }
    __syncthreads();
    if (slast) {
        __shared__ float ss[256], sc[256];
        __threadfence();
        float s = 0.f, c = 0.f;
        for (int i = threadIdx.x; i < K1_BLOCKS; i += 256) {
            float2 v = g_part[i];
            s += v.x; c += v.y;
        }
        ss[threadIdx.x] = s; sc[threadIdx.x] = c;
        __syncthreads();
        for (int st = 128; st; st >>= 1) {
            if (threadIdx.x < st) {
                ss[threadIdx.x] += ss[threadIdx.x + st];
                sc[threadIdx.x] += sc[threadIdx.x + st];
            }
            __syncthreads();
        }
        if (threadIdx.x == 0) out[0] = ss[0] / sc[0];
    }
}

// ============================================================================
extern "C" void kernel_launch(void* const* d_in, const int* in_sizes, int n_in,
                              void* d_out, int out_size) {
    const int*   items   = (const int*)d_in[0];
    const int*   actions = (const int*)d_in[1];
    const float* WihT    = (const float*)d_in[2];
    const float* Whh     = (const float*)d_in[3];
    const float* b_lstm  = (const float*)d_in[4];
    const float* temb    = (const float*)d_in[5];
    const float* Wq      = (const float*)d_in[6];
    const float* bq      = (const float*)d_in[7];
    (void)in_sizes; (void)n_in; (void)out_size;

    k1_prep<<<K1_BLOCKS, 256>>>(items, actions, WihT, b_lstm);
    knop<<<1, 1>>>();   // alignment: put k2_lstm at ncu's profiled slot (-s 5)
    knop<<<1, 1>>>();
    k2_lstm<<<NCL * CL, THR>>>(Whh);
    k3_loss<<<K1_BLOCKS, 256>>>(items, actions, temb, Wq, bq, (float*)d_out);
}

// round 8
// speedup vs baseline: 1.5089x; 1.2581x over previous
#include <cuda_runtime.h>
#include <cuda_bf16.h>
#include <cstdint>
#include <cstddef>

typedef unsigned long long ull;

#define B_  64
#define S_  200
#define T_  199
#define H_  256
#define G4  1024
#define NI_ 50000

#define CL  8           // CTAs per cluster
#define NCL 16          // clusters (16*4 = 64 batches)
#define THR 512
#define TXB 4096u       // expect_tx bytes per step: 8 CTAs x 64 owners x 8B
#define K1_BLOCKS 1592  // 1592*8 warps = 199*64 (b,t) pairs exactly

// ------------------------- device scratch (no allocs allowed) ---------------
__device__ __align__(16) float g_xp[(size_t)T_ * B_ * G4];      // xp + bias, [t][b][1024]
__device__ __align__(16) float g_states[(size_t)T_ * B_ * H_];  // masked h outputs [t][b][256]
__device__ unsigned char g_mask[T_ * B_];
__device__ unsigned g_k3done;
__device__ float2 g_part[K1_BLOCKS];

// ------------------------- helpers ------------------------------------------
__device__ __forceinline__ ull pk2(float lo, float hi) {
    ull r; asm("mov.b64 %0, {%1, %2};" : "=l"(r) : "f"(lo), "f"(hi)); return r;
}
__device__ __forceinline__ void upk2(ull v, float& lo, float& hi) {
    asm("mov.b64 {%0, %1}, %2;" : "=f"(lo), "=f"(hi) : "l"(v));
}
__device__ __forceinline__ void fma2(ull& acc, ull a, ull b) {
    asm("fma.rn.f32x2 %0, %1, %2, %0;" : "+l"(acc) : "l"(a), "l"(b));
}
__device__ __forceinline__ ull add2(ull a, ull b) {
    ull r; asm("add.rn.f32x2 %0, %1, %2;" : "=l"(r) : "l"(a), "l"(b)); return r;
}
__device__ __forceinline__ float sig_(float x) {
    return __fdividef(1.f, 1.f + __expf(-x));
}
__device__ __forceinline__ float tanh_(float x) {
    float a = fabsf(x);
    float e = __expf(-2.f * a);
    float r = __fdividef(1.f - e, 1.f + e);
    return copysignf(r, x);
}
__device__ __forceinline__ unsigned smem_u32(const void* p) {
    unsigned a;
    asm("{ .reg .u64 t; cvta.to.shared.u64 t, %1; cvt.u32.u64 %0, t; }" : "=r"(a) : "l"(p));
    return a;
}
__device__ __forceinline__ unsigned ctarank_() {
    unsigned r; asm("mov.u32 %0, %%cluster_ctarank;" : "=r"(r)); return r;
}
__device__ __forceinline__ unsigned mapa_(unsigned addr, unsigned rank) {
    unsigned r; asm("mapa.shared::cluster.u32 %0, %1, %2;" : "=r"(r) : "r"(addr), "r"(rank));
    return r;
}
__device__ __forceinline__ void mbar_init(unsigned addr, unsigned cnt) {
    asm volatile("mbarrier.init.shared.b64 [%0], %1;" :: "r"(addr), "r"(cnt) : "memory");
}
__device__ __forceinline__ void mbar_expect_tx(unsigned addr, unsigned bytes) {
    asm volatile("mbarrier.arrive.expect_tx.shared.b64 _, [%0], %1;"
                 :: "r"(addr), "r"(bytes) : "memory");
}
// remote store whose completion posts tx bytes on the destination CTA's barrier
__device__ __forceinline__ void st_async64(unsigned raddr, ull v, unsigned rmbar) {
    asm volatile("st.async.shared::cluster.mbarrier::complete_tx::bytes.b64 [%0], %1, [%2];"
                 :: "r"(raddr), "l"(v), "r"(rmbar) : "memory");
}
__device__ __forceinline__ void mbar_wait(unsigned addr, int parity) {
    asm volatile(
        "{\n\t.reg .pred P;\n\t"
        "WL_%=:\n\t"
        "mbarrier.try_wait.parity.acquire.cta.shared::cta.b64 P, [%0], %1, 0x989680;\n\t"
        "@P bra.uni WD_%=;\n\t"
        "bra.uni WL_%=;\n\t"
        "WD_%=:\n\t}"
        :: "r"(addr), "r"(parity) : "memory");
}
__device__ __forceinline__ void cluster_sync_() {
    asm volatile("barrier.cluster.arrive.aligned;" ::: "memory");
    asm volatile("barrier.cluster.wait.aligned;" ::: "memory");
}

// ============================================================================
// K1: x_proj (+bias) -> g_xp, mask bytes, reset k3 flag. One warp per (b,t).
// ============================================================================
__global__ void k1_prep(const int* __restrict__ items, const int* __restrict__ actions,
                        const float* __restrict__ WihT, const float* __restrict__ b_lstm) {
    if (blockIdx.x == 0 && threadIdx.x == 0) g_k3done = 0u;
    int gw = blockIdx.x * 8 + (threadIdx.x >> 5);
    int lane = threadIdx.x & 31;
    if (gw >= T_ * B_) return;
    int b = gw & 63, t = gw >> 6;
    int it = items[b * S_ + t];
    int ac = actions[b * S_ + t];
    bool m = (it != 0);
    const float4* ra = (const float4*)(WihT + (size_t)it * G4);
    const float4* rb = (const float4*)(WihT + (size_t)(NI_ + ac) * G4);
    const float4* bi = (const float4*)b_lstm;
    float4* dst = (float4*)(g_xp + ((size_t)t * B_ + b) * G4);
#pragma unroll
    for (int p = 0; p < 8; p++) {
        int idx = lane + 32 * p;
        float4 bv = bi[idx];
        float4 o;
        if (m) {
            float4 a = ra[idx], c = rb[idx];
            o = make_float4(a.x + c.x + bv.x, a.y + c.y + bv.y,
                            a.z + c.z + bv.z, a.w + c.w + bv.w);
        } else {
            o = bv;
        }
        dst[idx] = o;
    }
    if (lane == 0) g_mask[t * B_ + b] = m ? 1 : 0;
}

// profiling-alignment no-ops (2 launches so ncu -s 5 -c 1 lands on k2_lstm)
__global__ void knop() {}

// ============================================================================
// K2: LSTM recurrence. 16 independent clusters of 8 CTAs; cluster owns 4
// batches. CTA rank r owns 128 gate rows (32 h-elems x 4 gates), K=256.
// h exchange: st.async (tx-completing DSMEM stores) into peers' double-
// buffered h tiles; mbarrier armed with expect_tx(4096) per phase.
// ============================================================================
__global__ void __launch_bounds__(THR, 1) __cluster_dims__(CL, 1, 1)
k2_lstm(const float* __restrict__ Whh) {
    __shared__ __align__(16) float smh[2][256][4];   // h double buffer [buf][j][batch]
    __shared__ __align__(16) ull  smp[8][128][2];    // partials [ks][col][pair]
    __shared__ __align__(16) ull  smg[256];          // gates [g*64 + e*2 + pa]
    __shared__ __align__(8)  ull  mbar[2];

    const int tid = threadIdx.x;
    const unsigned rank = ctarank_();
    const int b0 = (blockIdx.x >> 3) * 4;

    const int ks = tid >> 6;        // K-slice (32 j's)
    const int u  = tid & 63;        // first col; second col = u+64

    // zero both h buffers; init + pre-arm barriers
    for (int i = tid; i < 512; i += THR)
        ((float4*)smh)[i] = make_float4(0.f, 0.f, 0.f, 0.f);
    if (tid < 2) mbar_init(smem_u32(&mbar[tid]), 1);
    __syncthreads();
    if (tid == 0) {
        mbar_expect_tx(smem_u32(&mbar[0]), TXB);   // for wait at t=2
        mbar_expect_tx(smem_u32(&mbar[1]), TXB);   // for wait at t=1
    }
    __syncthreads();
    cluster_sync_();   // arming + zeroed tiles visible before any peer store

    // weights for cols u and u+64 over K-slice: col c -> row (c>>5)*256+32*rank+(c&31)
    float W1[32], W2[32];
    {
        const int r1 = ((u >> 5) & 3) * 256 + 32 * (int)rank + (u & 31);
        const int r2 = (((u + 64) >> 5) & 3) * 256 + 32 * (int)rank + (u & 31);
        const float4* p1 = (const float4*)(Whh + (size_t)r1 * H_ + ks * 32);
        const float4* p2 = (const float4*)(Whh + (size_t)r2 * H_ + ks * 32);
#pragma unroll
        for (int q4 = 0; q4 < 8; q4++) {
            float4 v = p1[q4];
            W1[q4 * 4 + 0] = v.x; W1[q4 * 4 + 1] = v.y; W1[q4 * 4 + 2] = v.z; W1[q4 * 4 + 3] = v.w;
            float4 w = p2[q4];
            W2[q4 * 4 + 0] = w.x; W2[q4 * 4 + 1] = w.y; W2[q4 * 4 + 2] = w.z; W2[q4 * 4 + 3] = w.w;
        }
    }

    // reducer role (tid < 256): (rc = tid>>1 in [0,128) col, rpa = tid&1)
    const int rc = tid >> 1, rpa = tid & 1;
    const int Rr = (rc >> 5) * 256 + 32 * (int)rank + (rc & 31);
    const float* xpp = g_xp + (size_t)(b0 + 2 * rpa) * G4 + Rr;
    float xa = 0.f, xb = 0.f;
    if (tid < 256) { xa = xpp[0]; xb = xpp[G4]; }

    // owner role (tid < 64): (oe = tid>>1 in [0,32), opa = tid&1)
    const int oe = tid >> 1, opa = tid & 1;
    const int jg = 32 * (int)rank + oe;           // global h index owned
    float c0 = 0.f, c1 = 0.f, h0 = 0.f, h1 = 0.f;
    uchar2 mv = make_uchar2(0, 0);
    if (tid < 64) mv = *(const uchar2*)(g_mask + b0 + 2 * opa);

    const unsigned mb0 = smem_u32(&mbar[0]);
    const unsigned mb1 = smem_u32(&mbar[1]);
    int ph0 = 0, ph1 = 0;

    for (int t = 0; t < T_; t++) {
        const int buf = t & 1;
        if (t > 0) {
            if (buf) { mbar_wait(mb1, ph1); ph1 ^= 1; }
            else     { mbar_wait(mb0, ph0); ph0 ^= 1; }
            // re-arm this barrier for t+2, from an idle waiter warp (off critical path)
            if (tid == 256) mbar_expect_tx(buf ? mb1 : mb0, TXB);
        }

        // ---- compute: 4 accumulators (2 cols x 2 batch-pairs) ----
        ull a10 = 0, a11 = 0, a20 = 0, a21 = 0;
        {
            const ulonglong2* hb = (const ulonglong2*)&smh[buf][ks * 32][0];
#pragma unroll
            for (int jj = 0; jj < 32; jj++) {
                ulonglong2 hx = hb[jj];          // batch pairs {0,1},{2,3}
                ull w1 = pk2(W1[jj], W1[jj]);
                ull w2 = pk2(W2[jj], W2[jj]);
                fma2(a10, w1, hx.x); fma2(a11, w1, hx.y);
                fma2(a20, w2, hx.x); fma2(a21, w2, hx.y);
            }
        }
        *(ulonglong2*)&smp[ks][u][0]      = make_ulonglong2(a10, a11);
        *(ulonglong2*)&smp[ks][u + 64][0] = make_ulonglong2(a20, a21);
        __syncthreads();

        // ---- reducers (256 thr): sum 8 K-slices + xp -> smg ----
        if (tid < 256) {
            ull s = smp[0][rc][rpa];
#pragma unroll
            for (int k = 1; k < 8; k++) s = add2(s, smp[k][rc][rpa]);
            s = add2(s, pk2(xa, xb));
            smg[(rc >> 5) * 64 + (rc & 31) * 2 + rpa] = s;   // [g][e][pa]
            asm volatile("bar.sync 1, 256;" ::: "memory");
        }

        // ---- owners (64 thr): activations, state update, st.async broadcast ----
        if (tid < 64) {
            float i0, i1, f0, f1, gg0, gg1, o0, o1;
            upk2(smg[0 * 64 + oe * 2 + opa], i0, i1);
            upk2(smg[1 * 64 + oe * 2 + opa], f0, f1);
            upk2(smg[2 * 64 + oe * 2 + opa], gg0, gg1);
            upk2(smg[3 * 64 + oe * 2 + opa], o0, o1);

            float out0, out1;
            {
                float ii = sig_(i0), ff = sig_(f0), gt = tanh_(gg0), oo = sig_(o0);
                float cn = ff * c0 + ii * gt;
                float hn = oo * tanh_(cn);
                if (mv.x) { c0 = cn; h0 = hn; out0 = hn; } else out0 = 0.f;
            }
            {
                float ii = sig_(i1), ff = sig_(f1), gt = tanh_(gg1), oo = sig_(o1);
                float cn = ff * c1 + ii * gt;
                float hn = oo * tanh_(cn);
                if (mv.y) { c1 = cn; h1 = hn; out1 = hn; } else out1 = 0.f;
            }

            if (t + 1 < T_) {
                ull hull = pk2(h0, h1);
                unsigned loc = smem_u32(&smh[1 - buf][jg][2 * opa]);
                unsigned mbn = buf ? mb0 : mb1;
#pragma unroll
                for (int rr = 0; rr < CL; rr++)
                    st_async64(mapa_(loc, rr), hull, mapa_(mbn, rr));
            }

            // off critical path: states store + mask prefetch
            float* sp = g_states + ((size_t)t * B_ + b0 + 2 * opa) * H_ + jg;
            sp[0]  = out0;
            sp[H_] = out1;
            if (t + 1 < T_)
                mv = *(const uchar2*)(g_mask + (t + 1) * B_ + b0 + 2 * opa);
        }
        // reducers: prefetch xp(t+1) (off critical path)
        if (tid < 256 && t + 1 < T_) {
            const float* xp = xpp + (size_t)(t + 1) * B_ * G4;
            xa = xp[0]; xb = xp[G4];
        }
        // threads 256..511 fall straight through to the next mbarrier wait
    }
    cluster_sync_();  // no CTA exits while peers' remote ops may be in flight
}

// ============================================================================
// K3: query logits + per-(b,t) NLL; block partials + fused deterministic
// last-block final reduction. One warp per (b,t).
// ============================================================================
__global__ void k3_loss(const int* __restrict__ items, const int* __restrict__ actions,
                        const float* __restrict__ temb, const float* __restrict__ Wq,
                        const float* __restrict__ bq, float* __restrict__ out) {
    __shared__ float2 sred[8];
    __shared__ unsigned slast;
    int gw = blockIdx.x * 8 + (threadIdx.x >> 5);
    int lane = threadIdx.x & 31;
    float nll = 0.f, cnt = 0.f;
    int b = gw & 63, t = gw >> 6;
    int qit = items[b * S_ + t + 1];
    if (qit != 0) {
        const float4* sv = (const float4*)(g_states + ((size_t)t * B_ + b) * H_);
        const float4* ev = (const float4*)(temb + (size_t)qit * H_);
        const float4* w0 = (const float4*)Wq;
        const float4* w1 = (const float4*)(Wq + H_);
        float d0 = 0.f, d1 = 0.f;
#pragma unroll
        for (int p = 0; p < 2; p++) {
            int idx = lane * 2 + p;
            float4 s = sv[idx], e = ev[idx], a = w0[idx], c = w1[idx];
            float es;
            es = e.x * s.x; d0 += es * a.x; d1 += es * c.x;
            es = e.y * s.y; d0 += es * a.y; d1 += es * c.y;
            es = e.z * s.z; d0 += es * a.z; d1 += es * c.z;
            es = e.w * s.w; d0 += es * a.w; d1 += es * c.w;
        }
        ull d = pk2(d0, d1);
#pragma unroll
        for (int off = 16; off; off >>= 1)
            d = add2(d, __shfl_xor_sync(0xffffffffu, d, off));
        upk2(d, d0, d1);
        if (lane == 0) {
            float q0 = d0 + bq[0], q1 = d1 + bq[1];
            int tgt = actions[b * S_ + t + 1];
            float mx = fmaxf(q0, q1), mn = fminf(q0, q1);
            float lse = mx + log1pf(__expf(mn - mx));
            nll = lse - (tgt ? q1 : q0);
            cnt = 1.f;
        }
    }
    if (lane == 0) sred[threadIdx.x >> 5] = make_float2(nll, cnt);
    __syncthreads();
    if (threadIdx.x == 0) {
        float s = 0.f, c = 0.f;
#pragma unroll
        for (int i = 0; i < 8; i++) { s += sred[i].x; c += sred[i].y; }
        g_part[blockIdx.x] = make_float2(s, c);
        __threadfence();
        unsigned o = atomicAdd(&g_k3done, 1u);
        slast = (o == K1_BLOCKS - 1) ? 1u : 0u;
    }
    __syncthreads();
    if (slast) {
        __shared__ float ss[256], sc[256];
        __threadfence();
        float s = 0.f, c = 0.f;
        for (int i = threadIdx.x; i < K1_BLOCKS; i += 256) {
            float2 v = g_part[i];
            s += v.x; c += v.y;
        }
        ss[threadIdx.x] = s; sc[threadIdx.x] = c;
        __syncthreads();
        for (int st = 128; st; st >>= 1) {
            if (threadIdx.x < st) {
                ss[threadIdx.x] += ss[threadIdx.x + st];
                sc[threadIdx.x] += sc[threadIdx.x + st];
            }
            __syncthreads();
        }
        if (threadIdx.x == 0) out[0] = ss[0] / sc[0];
    }
}

// ============================================================================
extern "C" void kernel_launch(void* const* d_in, const int* in_sizes, int n_in,
                              void* d_out, int out_size) {
    const int*   items   = (const int*)d_in[0];
    const int*   actions = (const int*)d_in[1];
    const float* WihT    = (const float*)d_in[2];
    const float* Whh     = (const float*)d_in[3];
    const float* b_lstm  = (const float*)d_in[4];
    const float* temb    = (const float*)d_in[5];
    const float* Wq      = (const float*)d_in[6];
    const float* bq      = (const float*)d_in[7];
    (void)in_sizes; (void)n_in; (void)out_size;

    k1_prep<<<K1_BLOCKS, 256>>>(items, actions, WihT, b_lstm);
    knop<<<1, 1>>>();   // alignment: put k2_lstm at ncu's profiled slot (-s 5)
    knop<<<1, 1>>>();
    k2_lstm<<<NCL * CL, THR>>>(Whh);
    k3_loss<<<K1_BLOCKS, 256>>>(items, actions, temb, Wq, bq, (float*)d_out);
}

// round 9
// speedup vs baseline: 1.5237x; 1.0098x over previous
#include <cuda_runtime.h>
#include <cuda_bf16.h>
#include <cstdint>
#include <cstddef>

typedef unsigned long long ull;

#define B_  64
#define S_  200
#define T_  199
#define H_  256
#define G4  1024
#define NI_ 50000

#define CL  8           // CTAs per cluster
#define NCL 16          // clusters (16*4 = 64 batches)
#define THR 512
#define TXB 4096u       // expect_tx bytes per step: 8 CTAs x 64 owners x 8B
#define K1_BLOCKS 1592  // 1592*8 warps = 199*64 (b,t) pairs exactly

// ------------------------- device scratch (no allocs allowed) ---------------
__device__ __align__(16) float g_xp[(size_t)T_ * B_ * G4];      // xp + bias, [t][b][1024]
__device__ __align__(16) float g_states[(size_t)T_ * B_ * H_];  // masked h outputs [t][b][256]
__device__ unsigned char g_mask[T_ * B_];
__device__ unsigned g_k3done;
__device__ float2 g_part[K1_BLOCKS];

// ------------------------- helpers ------------------------------------------
__device__ __forceinline__ ull pk2(float lo, float hi) {
    ull r; asm("mov.b64 %0, {%1, %2};" : "=l"(r) : "f"(lo), "f"(hi)); return r;
}
__device__ __forceinline__ void upk2(ull v, float& lo, float& hi) {
    asm("mov.b64 {%0, %1}, %2;" : "=f"(lo), "=f"(hi) : "l"(v));
}
__device__ __forceinline__ void fma2(ull& acc, ull a, ull b) {
    asm("fma.rn.f32x2 %0, %1, %2, %0;" : "+l"(acc) : "l"(a), "l"(b));
}
__device__ __forceinline__ ull add2(ull a, ull b) {
    ull r; asm("add.rn.f32x2 %0, %1, %2;" : "=l"(r) : "l"(a), "l"(b)); return r;
}
__device__ __forceinline__ float tanha(float x) {
    float y; asm("tanh.approx.f32 %0, %1;" : "=f"(y) : "f"(x)); return y;
}
__device__ __forceinline__ float siga(float x) {
    return fmaf(tanha(0.5f * x), 0.5f, 0.5f);
}
__device__ __forceinline__ unsigned smem_u32(const void* p) {
    unsigned a;
    asm("{ .reg .u64 t; cvta.to.shared.u64 t, %1; cvt.u32.u64 %0, t; }" : "=r"(a) : "l"(p));
    return a;
}
__device__ __forceinline__ unsigned ctarank_() {
    unsigned r; asm("mov.u32 %0, %%cluster_ctarank;" : "=r"(r)); return r;
}
__device__ __forceinline__ unsigned mapa_(unsigned addr, unsigned rank) {
    unsigned r; asm("mapa.shared::cluster.u32 %0, %1, %2;" : "=r"(r) : "r"(addr), "r"(rank));
    return r;
}
__device__ __forceinline__ void mbar_init(unsigned addr, unsigned cnt) {
    asm volatile("mbarrier.init.shared.b64 [%0], %1;" :: "r"(addr), "r"(cnt) : "memory");
}
__device__ __forceinline__ void mbar_expect_tx(unsigned addr, unsigned bytes) {
    asm volatile("mbarrier.arrive.expect_tx.shared.b64 _, [%0], %1;"
                 :: "r"(addr), "r"(bytes) : "memory");
}
// remote store whose completion posts tx bytes on the destination CTA's barrier
__device__ __forceinline__ void st_async64(unsigned raddr, ull v, unsigned rmbar) {
    asm volatile("st.async.shared::cluster.mbarrier::complete_tx::bytes.b64 [%0], %1, [%2];"
                 :: "r"(raddr), "l"(v), "r"(rmbar) : "memory");
}
__device__ __forceinline__ void mbar_wait(unsigned addr, int parity) {
    asm volatile(
        "{\n\t.reg .pred P;\n\t"
        "WL_%=:\n\t"
        "mbarrier.try_wait.parity.acquire.cta.shared::cta.b64 P, [%0], %1, 0x989680;\n\t"
        "@P bra.uni WD_%=;\n\t"
        "bra.uni WL_%=;\n\t"
        "WD_%=:\n\t}"
        :: "r"(addr), "r"(parity) : "memory");
}
__device__ __forceinline__ void cluster_sync_() {
    asm volatile("barrier.cluster.arrive.aligned;" ::: "memory");
    asm volatile("barrier.cluster.wait.aligned;" ::: "memory");
}

// ============================================================================
// K1: x_proj (+bias) -> g_xp, mask bytes, reset k3 flag. One warp per (b,t).
// ============================================================================
__global__ void k1_prep(const int* __restrict__ items, const int* __restrict__ actions,
                        const float* __restrict__ WihT, const float* __restrict__ b_lstm) {
    if (blockIdx.x == 0 && threadIdx.x == 0) g_k3done = 0u;
    int gw = blockIdx.x * 8 + (threadIdx.x >> 5);
    int lane = threadIdx.x & 31;
    if (gw >= T_ * B_) return;
    int b = gw & 63, t = gw >> 6;
    int it = items[b * S_ + t];
    int ac = actions[b * S_ + t];
    bool m = (it != 0);
    const float4* ra = (const float4*)(WihT + (size_t)it * G4);
    const float4* rb = (const float4*)(WihT + (size_t)(NI_ + ac) * G4);
    const float4* bi = (const float4*)b_lstm;
    float4* dst = (float4*)(g_xp + ((size_t)t * B_ + b) * G4);
#pragma unroll
    for (int p = 0; p < 8; p++) {
        int idx = lane + 32 * p;
        float4 bv = bi[idx];
        float4 o;
        if (m) {
            float4 a = ra[idx], c = rb[idx];
            o = make_float4(a.x + c.x + bv.x, a.y + c.y + bv.y,
                            a.z + c.z + bv.z, a.w + c.w + bv.w);
        } else {
            o = bv;
        }
        dst[idx] = o;
    }
    if (lane == 0) g_mask[t * B_ + b] = m ? 1 : 0;
}

// profiling-alignment no-ops (2 launches so ncu -s 5 -c 1 lands on k2_lstm)
__global__ void knop() {}

// ============================================================================
// K2: LSTM recurrence. 16 independent clusters of 8 CTAs; cluster owns 4
// batches. CTA rank r owns 128 gate rows (32 h-elems x 4 gates), K=256.
// h exchange: st.async into peers' double-buffered h tiles (expect_tx 4096).
// Per-step sync: mbar wait + ONE named barrier (producers arrive-only).
// ============================================================================
__global__ void __launch_bounds__(THR, 1) __cluster_dims__(CL, 1, 1)
k2_lstm(const float* __restrict__ Whh) {
    __shared__ __align__(16) float smh[2][256][4];   // h double buffer [buf][j][batch]
    __shared__ __align__(16) ull  smp[8][128][2];    // partials [ks][col][pair]
    __shared__ __align__(8)  ull  mbar[2];

    const int tid = threadIdx.x;
    const unsigned rank = ctarank_();
    const int b0 = (blockIdx.x >> 3) * 4;

    const int ks = tid >> 6;        // K-slice (32 j's)
    const int u  = tid & 63;        // first col; second col = u+64

    // zero both h buffers; init + pre-arm barriers
    for (int i = tid; i < 512; i += THR)
        ((float4*)smh)[i] = make_float4(0.f, 0.f, 0.f, 0.f);
    if (tid < 2) mbar_init(smem_u32(&mbar[tid]), 1);
    __syncthreads();
    if (tid == 0) {
        mbar_expect_tx(smem_u32(&mbar[0]), TXB);   // for wait at t=2
        mbar_expect_tx(smem_u32(&mbar[1]), TXB);   // for wait at t=1
    }
    __syncthreads();
    cluster_sync_();   // arming + zeroed tiles visible before any peer store

    // weights: col c -> global row (c>>5)*256 + 32*rank + (c&31)
    // W1 pre-packed {v,v} (64 regs), W2 float (packed per-iter: 1 MOV)
    ull   W1p[32];
    float W2[32];
    {
        const int r1 = ((u >> 5) & 3) * 256 + 32 * (int)rank + (u & 31);
        const int r2 = (((u + 64) >> 5) & 3) * 256 + 32 * (int)rank + (u & 31);
        const float4* p1 = (const float4*)(Whh + (size_t)r1 * H_ + ks * 32);
        const float4* p2 = (const float4*)(Whh + (size_t)r2 * H_ + ks * 32);
#pragma unroll
        for (int q4 = 0; q4 < 8; q4++) {
            float4 v = p1[q4];
            W1p[q4 * 4 + 0] = pk2(v.x, v.x); W1p[q4 * 4 + 1] = pk2(v.y, v.y);
            W1p[q4 * 4 + 2] = pk2(v.z, v.z); W1p[q4 * 4 + 3] = pk2(v.w, v.w);
            float4 w = p2[q4];
            W2[q4 * 4 + 0] = w.x; W2[q4 * 4 + 1] = w.y;
            W2[q4 * 4 + 2] = w.z; W2[q4 * 4 + 3] = w.w;
        }
    }

    // owner role (tid < 64): (oe = tid>>1 in [0,32), opa = tid&1)
    const int oe = tid >> 1, opa = tid & 1;
    const int jg = 32 * (int)rank + oe;           // global h index owned
    float c0 = 0.f, c1 = 0.f, h0 = 0.f, h1 = 0.f;
    uchar2 mv = make_uchar2(0, 0);
    float xq0a = 0.f, xq0b = 0.f, xq1a = 0.f, xq1b = 0.f,
          xq2a = 0.f, xq2b = 0.f, xq3a = 0.f, xq3b = 0.f;
    const float* xbase = g_xp + (size_t)(b0 + 2 * opa) * G4 + jg;  // +g*256; +G4 batch+1
    if (tid < 64) {
        xq0a = xbase[0];     xq0b = xbase[G4];
        xq1a = xbase[256];   xq1b = xbase[G4 + 256];
        xq2a = xbase[512];   xq2b = xbase[G4 + 512];
        xq3a = xbase[768];   xq3b = xbase[G4 + 768];
        mv = *(const uchar2*)(g_mask + b0 + 2 * opa);
    }

    const unsigned mb0 = smem_u32(&mbar[0]);
    const unsigned mb1 = smem_u32(&mbar[1]);
    int ph0 = 0, ph1 = 0;

    for (int t = 0; t < T_; t++) {
        const int buf = t & 1;
        if (t > 0) {
            if (buf) { mbar_wait(mb1, ph1); ph1 ^= 1; }
            else     { mbar_wait(mb0, ph0); ph0 ^= 1; }
            // re-arm this barrier for t+2, from an idle producer warp
            if (tid == 256) mbar_expect_tx(buf ? mb1 : mb0, TXB);
        }

        // ---- compute: 4 accumulators (2 cols x 2 batch-pairs) ----
        ull a10 = 0, a11 = 0, a20 = 0, a21 = 0;
        {
            const ulonglong2* hb = (const ulonglong2*)&smh[buf][ks * 32][0];
#pragma unroll
            for (int jj = 0; jj < 32; jj++) {
                ulonglong2 hx = hb[jj];          // batch pairs {0,1},{2,3}
                ull w2 = pk2(W2[jj], W2[jj]);
                fma2(a10, W1p[jj], hx.x); fma2(a11, W1p[jj], hx.y);
                fma2(a20, w2, hx.x);      fma2(a21, w2, hx.y);
            }
        }
        *(ulonglong2*)&smp[ks][u][0]      = make_ulonglong2(a10, a11);
        *(ulonglong2*)&smp[ks][u + 64][0] = make_ulonglong2(a20, a21);

        if (tid >= 64) {
            // producers: signal partials ready and flow through to next wait
            asm volatile("bar.arrive 2, %0;" :: "n"(THR) : "memory");
            continue;
        }
        // owners: wait for all producers' partials
        asm volatile("bar.sync 2, %0;" :: "n"(THR) : "memory");

        // ---- owners reduce 8 K-slices x 4 gates directly (32 LDS.64) ----
        ull s0 = smp[0][oe][opa],      s1 = smp[0][32 + oe][opa],
            s2 = smp[0][64 + oe][opa], s3 = smp[0][96 + oe][opa];
#pragma unroll
        for (int k = 1; k < 8; k++) {
            s0 = add2(s0, smp[k][oe][opa]);
            s1 = add2(s1, smp[k][32 + oe][opa]);
            s2 = add2(s2, smp[k][64 + oe][opa]);
            s3 = add2(s3, smp[k][96 + oe][opa]);
        }
        s0 = add2(s0, pk2(xq0a, xq0b));
        s1 = add2(s1, pk2(xq1a, xq1b));
        s2 = add2(s2, pk2(xq2a, xq2b));
        s3 = add2(s3, pk2(xq3a, xq3b));

        float i0, i1, f0, f1, gg0, gg1, o0, o1;
        upk2(s0, i0, i1); upk2(s1, f0, f1); upk2(s2, gg0, gg1); upk2(s3, o0, o1);

        float out0, out1;
        {
            float ii = siga(i0), ff = siga(f0), gt = tanha(gg0), oo = siga(o0);
            float cn = ff * c0 + ii * gt;
            float hn = oo * tanha(cn);
            if (mv.x) { c0 = cn; h0 = hn; out0 = hn; } else out0 = 0.f;
        }
        {
            float ii = siga(i1), ff = siga(f1), gt = tanha(gg1), oo = siga(o1);
            float cn = ff * c1 + ii * gt;
            float hn = oo * tanha(cn);
            if (mv.y) { c1 = cn; h1 = hn; out1 = hn; } else out1 = 0.f;
        }

        // broadcast h first (critical path), then stores/prefetch
        if (t + 1 < T_) {
            ull hull = pk2(h0, h1);
            unsigned loc = smem_u32(&smh[1 - buf][jg][2 * opa]);
            unsigned mbn = buf ? mb0 : mb1;
#pragma unroll
            for (int rr = 0; rr < CL; rr++)
                st_async64(mapa_(loc, rr), hull, mapa_(mbn, rr));
        }

        float* sp = g_states + ((size_t)t * B_ + b0 + 2 * opa) * H_ + jg;
        sp[0]  = out0;
        sp[H_] = out1;
        if (t + 1 < T_) {
            const float* xp = xbase + (size_t)(t + 1) * B_ * G4;
            xq0a = xp[0];     xq0b = xp[G4];
            xq1a = xp[256];   xq1b = xp[G4 + 256];
            xq2a = xp[512];   xq2b = xp[G4 + 512];
            xq3a = xp[768];   xq3b = xp[G4 + 768];
            mv = *(const uchar2*)(g_mask + (t + 1) * B_ + b0 + 2 * opa);
        }
    }
    cluster_sync_();  // no CTA exits while peers' remote ops may be in flight
}

// ============================================================================
// K3: query logits + per-(b,t) NLL; block partials + fused deterministic
// last-block final reduction. One warp per (b,t).
// ============================================================================
__global__ void k3_loss(const int* __restrict__ items, const int* __restrict__ actions,
                        const float* __restrict__ temb, const float* __restrict__ Wq,
                        const float* __restrict__ bq, float* __restrict__ out) {
    __shared__ float2 sred[8];
    __shared__ unsigned slast;
    int gw = blockIdx.x * 8 + (threadIdx.x >> 5);
    int lane = threadIdx.x & 31;
    float nll = 0.f, cnt = 0.f;
    int b = gw & 63, t = gw >> 6;
    int qit = items[b * S_ + t + 1];
    if (qit != 0) {
        const float4* sv = (const float4*)(g_states + ((size_t)t * B_ + b) * H_);
        const float4* ev = (const float4*)(temb + (size_t)qit * H_);
        const float4* w0 = (const float4*)Wq;
        const float4* w1 = (const float4*)(Wq + H_);
        float d0 = 0.f, d1 = 0.f;
#pragma unroll
        for (int p = 0; p < 2; p++) {
            int idx = lane * 2 + p;
            float4 s = sv[idx], e = ev[idx], a = w0[idx], c = w1[idx];
            float es;
            es = e.x * s.x; d0 += es * a.x; d1 += es * c.x;
            es = e.y * s.y; d0 += es * a.y; d1 += es * c.y;
            es = e.z * s.z; d0 += es * a.z; d1 += es * c.z;
            es = e.w * s.w; d0 += es * a.w; d1 += es * c.w;
        }
        ull d = pk2(d0, d1);
#pragma unroll
        for (int off = 16; off; off >>= 1)
            d = add2(d, __shfl_xor_sync(0xffffffffu, d, off));
        upk2(d, d0, d1);
        if (lane == 0) {
            float q0 = d0 + bq[0], q1 = d1 + bq[1];
            int tgt = actions[b * S_ + t + 1];
            float mx = fmaxf(q0, q1), mn = fminf(q0, q1);
            float lse = mx + log1pf(__expf(mn - mx));
            nll = lse - (tgt ? q1 : q0);
            cnt = 1.f;
        }
    }
    if (lane == 0) sred[threadIdx.x >> 5] = make_float2(nll, cnt);
    __syncthreads();
    if (threadIdx.x == 0) {
        float s = 0.f, c = 0.f;
#pragma unroll
        for (int i = 0; i < 8; i++) { s += sred[i].x; c += sred[i].y; }
        g_part[blockIdx.x] = make_float2(s, c);
        __threadfence();
        unsigned o = atomicAdd(&g_k3done, 1u);
        slast = (o == K1_BLOCKS - 1) ? 1u : 0u;
    }
    __syncthreads();
    if (slast) {
        __shared__ float ss[256], sc[256];
        __threadfence();
        float s = 0.f, c = 0.f;
        for (int i = threadIdx.x; i < K1_BLOCKS; i += 256) {
            float2 v = g_part[i];
            s += v.x; c += v.y;
        }
        ss[threadIdx.x] = s; sc[threadIdx.x] = c;
        __syncthreads();
        for (int st = 128; st; st >>= 1) {
            if (threadIdx.x < st) {
                ss[threadIdx.x] += ss[threadIdx.x + st];
                sc[threadIdx.x] += sc[threadIdx.x + st];
            }
            __syncthreads();
        }
        if (threadIdx.x == 0) out[0] = ss[0] / sc[0];
    }
}

// ============================================================================
extern "C" void kernel_launch(void* const* d_in, const int* in_sizes, int n_in,
                              void* d_out, int out_size) {
    const int*   items   = (const int*)d_in[0];
    const int*   actions = (const int*)d_in[1];
    const float* WihT    = (const float*)d_in[2];
    const float* Whh     = (const float*)d_in[3];
    const float* b_lstm  = (const float*)d_in[4];
    const float* temb    = (const float*)d_in[5];
    const float* Wq      = (const float*)d_in[6];
    const float* bq      = (const float*)d_in[7];
    (void)in_sizes; (void)n_in; (void)out_size;

    k1_prep<<<K1_BLOCKS, 256>>>(items, actions, WihT, b_lstm);
    knop<<<1, 1>>>();   // alignment: put k2_lstm at ncu's profiled slot (-s 5)
    knop<<<1, 1>>>();
    k2_lstm<<<NCL * CL, THR>>>(Whh);
    k3_loss<<<K1_BLOCKS, 256>>>(items, actions, temb, Wq, bq, (float*)d_out);
}

// round 11
// speedup vs baseline: 1.7678x; 1.1603x over previous
#include <cuda_runtime.h>
#include <cuda_bf16.h>
#include <cstdint>
#include <cstddef>

typedef unsigned long long ull;

#define B_  64
#define S_  200
#define T_  199
#define H_  256
#define G4  1024
#define NI_ 50000

#define CL  8           // CTAs per cluster
#define NCL 16          // clusters (16*4 = 64 batches)
#define CPT 512         // compute threads
#define THR 576         // + 2 owner warps (subgroup A, subgroup B)
#define BARCNT 544      // 512 compute + 32 owners of one subgroup
#define TXB 2048u       // expect_tx: 8 CTAs x 32 owners x 8B per subgroup
#define K1_BLOCKS 1592  // 1592*8 warps = 199*64 (b,t) pairs exactly

// ------------------------- device scratch (no allocs allowed) ---------------
__device__ __align__(16) float g_xp[(size_t)T_ * B_ * G4];      // xp + bias, [t][b][1024]
__device__ __align__(16) float g_states[(size_t)T_ * B_ * H_];  // masked h outputs [t][b][256]
__device__ unsigned char g_mask[T_ * B_];
__device__ unsigned g_k3done;
__device__ float2 g_part[K1_BLOCKS];

// ------------------------- helpers ------------------------------------------
__device__ __forceinline__ ull pk2(float lo, float hi) {
    ull r; asm("mov.b64 %0, {%1, %2};" : "=l"(r) : "f"(lo), "f"(hi)); return r;
}
__device__ __forceinline__ void upk2(ull v, float& lo, float& hi) {
    asm("mov.b64 {%0, %1}, %2;" : "=f"(lo), "=f"(hi) : "l"(v));
}
__device__ __forceinline__ void fma2(ull& acc, ull a, ull b) {
    asm("fma.rn.f32x2 %0, %1, %2, %0;" : "+l"(acc) : "l"(a), "l"(b));
}
__device__ __forceinline__ ull add2(ull a, ull b) {
    ull r; asm("add.rn.f32x2 %0, %1, %2;" : "=l"(r) : "l"(a), "l"(b)); return r;
}
__device__ __forceinline__ float tanha(float x) {
    float y; asm("tanh.approx.f32 %0, %1;" : "=f"(y) : "f"(x)); return y;
}
__device__ __forceinline__ float siga(float x) {
    return fmaf(tanha(0.5f * x), 0.5f, 0.5f);
}
__device__ __forceinline__ unsigned smem_u32(const void* p) {
    unsigned a;
    asm("{ .reg .u64 t; cvta.to.shared.u64 t, %1; cvt.u32.u64 %0, t; }" : "=r"(a) : "l"(p));
    return a;
}
__device__ __forceinline__ unsigned ctarank_() {
    unsigned r; asm("mov.u32 %0, %%cluster_ctarank;" : "=r"(r)); return r;
}
__device__ __forceinline__ unsigned mapa_(unsigned addr, unsigned rank) {
    unsigned r; asm("mapa.shared::cluster.u32 %0, %1, %2;" : "=r"(r) : "r"(addr), "r"(rank));
    return r;
}
__device__ __forceinline__ void mbar_init(unsigned addr, unsigned cnt) {
    asm volatile("mbarrier.init.shared.b64 [%0], %1;" :: "r"(addr), "r"(cnt) : "memory");
}
__device__ __forceinline__ void mbar_expect_tx(unsigned addr, unsigned bytes) {
    asm volatile("mbarrier.arrive.expect_tx.shared.b64 _, [%0], %1;"
                 :: "r"(addr), "r"(bytes) : "memory");
}
// remote store whose completion posts tx bytes on the destination CTA's barrier
__device__ __forceinline__ void st_async64(unsigned raddr, ull v, unsigned rmbar) {
    asm volatile("st.async.shared::cluster.mbarrier::complete_tx::bytes.b64 [%0], %1, [%2];"
                 :: "r"(raddr), "l"(v), "r"(rmbar) : "memory");
}
__device__ __forceinline__ void mbar_wait(unsigned addr, int parity) {
    asm volatile(
        "{\n\t.reg .pred P;\n\t"
        "WL_%=:\n\t"
        "mbarrier.try_wait.parity.acquire.cta.shared::cta.b64 P, [%0], %1, 0x989680;\n\t"
        "@P bra.uni WD_%=;\n\t"
        "bra.uni WL_%=;\n\t"
        "WD_%=:\n\t}"
        :: "r"(addr), "r"(parity) : "memory");
}
__device__ __forceinline__ void cluster_sync_() {
    asm volatile("barrier.cluster.arrive.aligned;" ::: "memory");
    asm volatile("barrier.cluster.wait.aligned;" ::: "memory");
}

// ============================================================================
// K1: x_proj (+bias) -> g_xp, mask bytes, reset k3 flag. One warp per (b,t).
// ============================================================================
__global__ void k1_prep(const int* __restrict__ items, const int* __restrict__ actions,
                        const float* __restrict__ WihT, const float* __restrict__ b_lstm) {
    if (blockIdx.x == 0 && threadIdx.x == 0) g_k3done = 0u;
    int gw = blockIdx.x * 8 + (threadIdx.x >> 5);
    int lane = threadIdx.x & 31;
    if (gw >= T_ * B_) return;
    int b = gw & 63, t = gw >> 6;
    int it = items[b * S_ + t];
    int ac = actions[b * S_ + t];
    bool m = (it != 0);
    const float4* ra = (const float4*)(WihT + (size_t)it * G4);
    const float4* rb = (const float4*)(WihT + (size_t)(NI_ + ac) * G4);
    const float4* bi = (const float4*)b_lstm;
    float4* dst = (float4*)(g_xp + ((size_t)t * B_ + b) * G4);
#pragma unroll
    for (int p = 0; p < 8; p++) {
        int idx = lane + 32 * p;
        float4 bv = bi[idx];
        float4 o;
        if (m) {
            float4 a = ra[idx], c = rb[idx];
            o = make_float4(a.x + c.x + bv.x, a.y + c.y + bv.y,
                            a.z + c.z + bv.z, a.w + c.w + bv.w);
        } else {
            o = bv;
        }
        dst[idx] = o;
    }
    if (lane == 0) g_mask[t * B_ + b] = m ? 1 : 0;
}

// profiling-alignment no-ops (2 launches so ncu -s 5 -c 1 lands on k2_lstm)
__global__ void knop() {}

// ============================================================================
// K2: pipelined LSTM. 16 clusters x 8 CTAs; cluster owns 4 batches split
// into subgroups A={b0,b0+1}, B={b0+2,b0+3}. Same register-resident Whh
// serves both. Dedicated owner warps (2) per CTA; producers flow through.
// While B computes, A's exchange (owner + st.async + landing) hides, and
// vice versa -> step period ~ computeA + computeB.
// ============================================================================
__global__ void __launch_bounds__(THR, 1) __cluster_dims__(CL, 1, 1)
k2_lstm(const float* __restrict__ Whh) {
    __shared__ __align__(16) ull smh[2][2][256];   // [sg][buf][j] 2 batches packed
    __shared__ __align__(16) ull smp[2][8][128];   // [sg][ks][col]
    __shared__ __align__(8)  ull mbar[4];          // [sg*2+buf]

    const int tid = threadIdx.x;
    const unsigned rank = ctarank_();
    const int b0 = (blockIdx.x >> 3) * 4;

    // zero h buffers (8 KB); init + pre-arm all 4 barriers
    for (int i = tid; i < 512; i += THR)
        ((float4*)smh)[i] = make_float4(0.f, 0.f, 0.f, 0.f);
    if (tid < 4) mbar_init(smem_u32(&mbar[tid]), 1);
    __syncthreads();
    if (tid == 0) {
#pragma unroll
        for (int i = 0; i < 4; i++) mbar_expect_tx(smem_u32(&mbar[i]), TXB);
    }
    __syncthreads();
    cluster_sync_();   // arming + zeroed tiles visible before any peer store

    const unsigned mbA0 = smem_u32(&mbar[0]), mbA1 = smem_u32(&mbar[1]);
    const unsigned mbB0 = smem_u32(&mbar[2]), mbB1 = smem_u32(&mbar[3]);

    if (tid < CPT) {
        // ---------------- compute role ----------------
        const int ks = tid >> 6;    // K-slice: j in [32ks, 32ks+32)
        const int u  = tid & 63;    // cols u and u+64

        // weights: col c -> global row (c>>5)*256 + 32*rank + (c&31)
        ull   W1p[32];
        float W2[32];
        {
            const int r1 = ((u >> 5) & 3) * 256 + 32 * (int)rank + (u & 31);
            const int r2 = (((u + 64) >> 5) & 3) * 256 + 32 * (int)rank + (u & 31);
            const float4* p1 = (const float4*)(Whh + (size_t)r1 * H_ + ks * 32);
            const float4* p2 = (const float4*)(Whh + (size_t)r2 * H_ + ks * 32);
#pragma unroll
            for (int q4 = 0; q4 < 8; q4++) {
                float4 v = p1[q4];
                W1p[q4 * 4 + 0] = pk2(v.x, v.x); W1p[q4 * 4 + 1] = pk2(v.y, v.y);
                W1p[q4 * 4 + 2] = pk2(v.z, v.z); W1p[q4 * 4 + 3] = pk2(v.w, v.w);
                float4 w = p2[q4];
                W2[q4 * 4 + 0] = w.x; W2[q4 * 4 + 1] = w.y;
                W2[q4 * 4 + 2] = w.z; W2[q4 * 4 + 3] = w.w;
            }
        }

        for (int t = 0; t < T_; t++) {
            const int buf = t & 1;
            const int par = ((t >> 1) + (t & 1) + 1) & 1;  // parity of wait at step t

            // ---- subgroup A ----
            if (t > 0) mbar_wait(buf ? mbA1 : mbA0, par);
            {
                ull a1 = 0, a2 = 0;
                const ulonglong2* hb = (const ulonglong2*)&smh[0][buf][ks * 32];
#pragma unroll
                for (int j2 = 0; j2 < 16; j2++) {
                    ulonglong2 hx = hb[j2];
                    fma2(a1, W1p[2 * j2], hx.x);
                    fma2(a2, pk2(W2[2 * j2], W2[2 * j2]), hx.x);
                    fma2(a1, W1p[2 * j2 + 1], hx.y);
                    fma2(a2, pk2(W2[2 * j2 + 1], W2[2 * j2 + 1]), hx.y);
                }
                smp[0][ks][u]      = a1;
                smp[0][ks][u + 64] = a2;
            }
            asm volatile("bar.arrive 2, %0;" :: "n"(BARCNT) : "memory");

            // ---- subgroup B ----
            if (t > 0) mbar_wait(buf ? mbB1 : mbB0, par);
            {
                ull a1 = 0, a2 = 0;
                const ulonglong2* hb = (const ulonglong2*)&smh[1][buf][ks * 32];
#pragma unroll
                for (int j2 = 0; j2 < 16; j2++) {
                    ulonglong2 hx = hb[j2];
                    fma2(a1, W1p[2 * j2], hx.x);
                    fma2(a2, pk2(W2[2 * j2], W2[2 * j2]), hx.x);
                    fma2(a1, W1p[2 * j2 + 1], hx.y);
                    fma2(a2, pk2(W2[2 * j2 + 1], W2[2 * j2 + 1]), hx.y);
                }
                smp[1][ks][u]      = a1;
                smp[1][ks][u + 64] = a2;
            }
            asm volatile("bar.arrive 3, %0;" :: "n"(BARCNT) : "memory");
        }
    } else {
        // ---------------- owner role (2 warps: sg 0 = A, sg 1 = B) ----------
        const int ot = tid - CPT;          // 0..63
        const int sg = ot >> 5;            // subgroup
        const int e  = ot & 31;            // h-elem within CTA
        const int bA = b0 + 2 * sg;        // batch pair (bA, bA+1)
        const int jg = 32 * (int)rank + e; // global h index owned
        const unsigned mb0 = sg ? mbB0 : mbA0;
        const unsigned mb1 = sg ? mbB1 : mbA1;

        float c0 = 0.f, c1 = 0.f, h0 = 0.f, h1 = 0.f;
        uchar2 mv = *(const uchar2*)(g_mask + bA);
        const float* xb0 = g_xp + (size_t)bA * G4 + jg;   // + g*256; + G4 for bA+1
        float xq0a = xb0[0],   xq0b = xb0[G4];
        float xq1a = xb0[256], xq1b = xb0[G4 + 256];
        float xq2a = xb0[512], xq2b = xb0[G4 + 512];
        float xq3a = xb0[768], xq3b = xb0[G4 + 768];

        for (int t = 0; t < T_; t++) {
            const int buf = t & 1;
            const int par = ((t >> 1) + (t & 1) + 1) & 1;
            const unsigned mba = buf ? mb1 : mb0;
            if (t > 0) {
                mbar_wait(mba, par);                   // observe flip
                if (e == 0) mbar_expect_tx(mba, TXB);  // re-arm for t+2: ONE lane!
            }
            if (sg == 0)
                asm volatile("bar.sync 2, %0;" :: "n"(BARCNT) : "memory");
            else
                asm volatile("bar.sync 3, %0;" :: "n"(BARCNT) : "memory");

            // reduce 8 K-slices x 4 gates (32 conflict-free LDS.64)
            ull s0 = smp[sg][0][e],      s1 = smp[sg][0][32 + e],
                s2 = smp[sg][0][64 + e], s3 = smp[sg][0][96 + e];
#pragma unroll
            for (int k = 1; k < 8; k++) {
                s0 = add2(s0, smp[sg][k][e]);
                s1 = add2(s1, smp[sg][k][32 + e]);
                s2 = add2(s2, smp[sg][k][64 + e]);
                s3 = add2(s3, smp[sg][k][96 + e]);
            }
            s0 = add2(s0, pk2(xq0a, xq0b));
            s1 = add2(s1, pk2(xq1a, xq1b));
            s2 = add2(s2, pk2(xq2a, xq2b));
            s3 = add2(s3, pk2(xq3a, xq3b));

            float i0, i1, f0, f1, gg0, gg1, o0, o1;
            upk2(s0, i0, i1); upk2(s1, f0, f1); upk2(s2, gg0, gg1); upk2(s3, o0, o1);

            float out0, out1;
            {
                float ii = siga(i0), ff = siga(f0), gt = tanha(gg0), oo = siga(o0);
                float cn = ff * c0 + ii * gt;
                float hn = oo * tanha(cn);
                if (mv.x) { c0 = cn; h0 = hn; out0 = hn; } else out0 = 0.f;
            }
            {
                float ii = siga(i1), ff = siga(f1), gt = tanha(gg1), oo = siga(o1);
                float cn = ff * c1 + ii * gt;
                float hn = oo * tanha(cn);
                if (mv.y) { c1 = cn; h1 = hn; out1 = hn; } else out1 = 0.f;
            }

            // broadcast h(t+1) first (critical path)
            if (t + 1 < T_) {
                ull hull = pk2(h0, h1);
                unsigned loc = smem_u32(&smh[sg][1 - buf][jg]);
                unsigned mbn = buf ? mb0 : mb1;
#pragma unroll
                for (int rr = 0; rr < CL; rr++)
                    st_async64(mapa_(loc, rr), hull, mapa_(mbn, rr));
            }

            // off critical path: states store + next-step prefetch
            float* sp = g_states + ((size_t)t * B_ + bA) * H_ + jg;
            sp[0]  = out0;
            sp[H_] = out1;
            if (t + 1 < T_) {
                const float* xp = xb0 + (size_t)(t + 1) * B_ * G4;
                xq0a = xp[0];   xq0b = xp[G4];
                xq1a = xp[256]; xq1b = xp[G4 + 256];
                xq2a = xp[512]; xq2b = xp[G4 + 512];
                xq3a = xp[768]; xq3b = xp[G4 + 768];
                mv = *(const uchar2*)(g_mask + (t + 1) * B_ + bA);
            }
        }
    }
    cluster_sync_();  // no CTA exits while peers' remote ops may be in flight
}

// ============================================================================
// K3: query logits + per-(b,t) NLL; block partials + fused deterministic
// last-block final reduction. One warp per (b,t).
// ============================================================================
__global__ void k3_loss(const int* __restrict__ items, const int* __restrict__ actions,
                        const float* __restrict__ temb, const float* __restrict__ Wq,
                        const float* __restrict__ bq, float* __restrict__ out) {
    __shared__ float2 sred[8];
    __shared__ unsigned slast;
    int gw = blockIdx.x * 8 + (threadIdx.x >> 5);
    int lane = threadIdx.x & 31;
    float nll = 0.f, cnt = 0.f;
    int b = gw & 63, t = gw >> 6;
    int qit = items[b * S_ + t + 1];
    if (qit != 0) {
        const float4* sv = (const float4*)(g_states + ((size_t)t * B_ + b) * H_);
        const float4* ev = (const float4*)(temb + (size_t)qit * H_);
        const float4* w0 = (const float4*)Wq;
        const float4* w1 = (const float4*)(Wq + H_);
        float d0 = 0.f, d1 = 0.f;
#pragma unroll
        for (int p = 0; p < 2; p++) {
            int idx = lane * 2 + p;
            float4 s = sv[idx], e = ev[idx], a = w0[idx], c = w1[idx];
            float es;
            es = e.x * s.x; d0 += es * a.x; d1 += es * c.x;
            es = e.y * s.y; d0 += es * a.y; d1 += es * c.y;
            es = e.z * s.z; d0 += es * a.z; d1 += es * c.z;
            es = e.w * s.w; d0 += es * a.w; d1 += es * c.w;
        }
        ull d = pk2(d0, d1);
#pragma unroll
        for (int off = 16; off; off >>= 1)
            d = add2(d, __shfl_xor_sync(0xffffffffu, d, off));
        upk2(d, d0, d1);
        if (lane == 0) {
            float q0 = d0 + bq[0], q1 = d1 + bq[1];
            int tgt = actions[b * S_ + t + 1];
            float mx = fmaxf(q0, q1), mn = fminf(q0, q1);
            float lse = mx + log1pf(__expf(mn - mx));
            nll = lse - (tgt ? q1 : q0);
            cnt = 1.f;
        }
    }
    if (lane == 0) sred[threadIdx.x >> 5] = make_float2(nll, cnt);
    __syncthreads();
    if (threadIdx.x == 0) {
        float s = 0.f, c = 0.f;
#pragma unroll
        for (int i = 0; i < 8; i++) { s += sred[i].x; c += sred[i].y; }
        g_part[blockIdx.x] = make_float2(s, c);
        __threadfence();
        unsigned o = atomicAdd(&g_k3done, 1u);
        slast = (o == K1_BLOCKS - 1) ? 1u : 0u;
    }
    __syncthreads();
    if (slast) {
        __shared__ float ss[256], sc[256];
        __threadfence();
        float s = 0.f, c = 0.f;
        for (int i = threadIdx.x; i < K1_BLOCKS; i += 256) {
            float2 v = g_part[i];
            s += v.x; c += v.y;
        }
        ss[threadIdx.x] = s; sc[threadIdx.x] = c;
        __syncthreads();
        for (int st = 128; st; st >>= 1) {
            if (threadIdx.x < st) {
                ss[threadIdx.x] += ss[threadIdx.x + st];
                sc[threadIdx.x] += sc[threadIdx.x + st];
            }
            __syncthreads();
        }
        if (threadIdx.x == 0) out[0] = ss[0] / sc[0];
    }
}

// ============================================================================
extern "C" void kernel_launch(void* const* d_in, const int* in_sizes, int n_in,
                              void* d_out, int out_size) {
    const int*   items   = (const int*)d_in[0];
    const int*   actions = (const int*)d_in[1];
    const float* WihT    = (const float*)d_in[2];
    const float* Whh     = (const float*)d_in[3];
    const float* b_lstm  = (const float*)d_in[4];
    const float* temb    = (const float*)d_in[5];
    const float* Wq      = (const float*)d_in[6];
    const float* bq      = (const float*)d_in[7];
    (void)in_sizes; (void)n_in; (void)out_size;

    k1_prep<<<K1_BLOCKS, 256>>>(items, actions, WihT, b_lstm);
    knop<<<1, 1>>>();   // alignment: put k2_lstm at ncu's profiled slot (-s 5)
    knop<<<1, 1>>>();
    k2_lstm<<<NCL * CL, THR>>>(Whh);
    k3_loss<<<K1_BLOCKS, 256>>>(items, actions, temb, Wq, bq, (float*)d_out);
}